// round 7
// baseline (speedup 1.0000x reference)
#include <cuda_runtime.h>
#include <cuda_bf16.h>
#include <cstdint>

// Problem constants
#define B_   4
#define L_   2048
#define D_   1024
#define H_   16
#define DK_  64
#define M_   (B_*L_)      // 8192

static const long long OUT_ELEMS  = (long long)B_ * L_ * D_;        // 8388608
static const long long ATTN_ELEMS = (long long)B_ * H_ * L_ * L_;   // 268435456
#define NROWS  (64 * 2048)          // total attn rows (bh * q)
#define NTILES 16                   // k-tiles per row in scores

// Scratch (__device__ globals: allocation-free rule)
__device__ __nv_bfloat16 g_Qh[(size_t)M_ * D_];
__device__ __nv_bfloat16 g_Ql[(size_t)M_ * D_];
__device__ __nv_bfloat16 g_Kh[(size_t)M_ * D_];
__device__ __nv_bfloat16 g_Kl[(size_t)M_ * D_];
__device__ __nv_bfloat16 g_Vh[(size_t)M_ * D_];
__device__ __nv_bfloat16 g_Vl[(size_t)M_ * D_];
__device__ __nv_bfloat16 g_Vth[(size_t)B_ * D_ * L_];
__device__ __nv_bfloat16 g_Vtl[(size_t)B_ * D_ * L_];
__device__ __nv_bfloat16 g_ctxh[(size_t)M_ * D_];
__device__ __nv_bfloat16 g_ctxl[(size_t)M_ * D_];
__device__ __nv_bfloat16 g_Wth[(size_t)4 * D_ * D_];
__device__ __nv_bfloat16 g_Wtl[(size_t)4 * D_ * D_];
__device__ float g_scores[(size_t)B_ * H_ * L_ * L_];   // raw scaled scores
__device__ float g_pmax[(size_t)NTILES * NROWS];        // [tile][bh*L + q]
__device__ float g_psum[(size_t)NTILES * NROWS];
__device__ float g_stats[(size_t)NROWS * 2];            // [row]{max, 1/sum}

// ===========================================================================
// mma.sync helpers (PTX sm_80+, legal on the compute_103 base target)
// ===========================================================================
__device__ __forceinline__ void mma16816(float* d, const uint32_t* a, const uint32_t* b) {
    asm volatile(
        "mma.sync.aligned.m16n8k16.row.col.f32.bf16.bf16.f32 "
        "{%0,%1,%2,%3}, {%4,%5,%6,%7}, {%8,%9}, {%0,%1,%2,%3};"
        : "+f"(d[0]), "+f"(d[1]), "+f"(d[2]), "+f"(d[3])
        : "r"(a[0]), "r"(a[1]), "r"(a[2]), "r"(a[3]), "r"(b[0]), "r"(b[1]));
}

__device__ __forceinline__ uint32_t pack2f(float lo, float hi) {
    uint32_t r;
    asm("cvt.rn.bf16x2.f32 %0, %1, %2;" : "=r"(r) : "f"(hi), "f"(lo));
    return r;
}

// Load 8 consecutive fp32, split into hi/lo bf16 uint4 pairs.
__device__ __forceinline__ void split8(const float* src, uint4& hi, uint4& lo) {
    float4 u = *(const float4*)src;
    float4 w = *(const float4*)(src + 4);
    float xs[8] = {u.x, u.y, u.z, u.w, w.x, w.y, w.z, w.w};
    uint32_t h[4], l[4];
#pragma unroll
    for (int i = 0; i < 4; i++) {
        uint32_t hp = pack2f(xs[2*i], xs[2*i+1]);
        float h0 = __uint_as_float(hp << 16);
        float h1 = __uint_as_float(hp & 0xFFFF0000u);
        l[i] = pack2f(xs[2*i] - h0, xs[2*i+1] - h1);
        h[i] = hp;
    }
    hi.x = h[0]; hi.y = h[1]; hi.z = h[2]; hi.w = h[3];
    lo.x = l[0]; lo.y = l[1]; lo.z = l[2]; lo.w = l[3];
}

struct GemmParams {
    const void* A; const void* A2;                 // A (and lo plane for AMODE1)
    const __nv_bfloat16* Bh; const __nv_bfloat16* Bl;
    const float* bias;
    void* C; void* C2;                             // C2 = lo plane (OMODE1)
    float* pmax; float* psum;                      // OMODE2 partials
    const float* stats;                            // AMODE2 row stats
    float* attn_out;                               // AMODE2 normalized attn
    long long lda, ldb, ldc;
    int k_chunks;      // K / 64
    float scale;
    int z_lo;          // z = zh*z_lo + zl
    long long a_hi, a_lo, b_hi, b_lo, c_hi, c_lo;
};

// ===========================================================================
// Unified tensor-core GEMM: C[m0:128, n0:NC] = scale*(A@B^T) + bias
// AMODE 0: A fp32 -> split on load.  AMODE 1: A bf16 hi/lo planes (copy).
// AMODE 2: A fp32 raw scores -> exp(s-m)*inv, write attn, split to hi/lo.
// OMODE 0: C fp32 (+bias).  OMODE 1: C bf16 hi/lo planes (+bias).
// OMODE 2: C fp32 raw + per-tile row (max, sumexp) partials.
// B always bf16 hi/lo planes. 3 MMA passes: hh, hl, lh.
// Smem: [rows][72] bf16 (pitch 144B) -> conflict-free fragment LDS.
// ===========================================================================
#define KPITCH 72

template<int NC, int AMODE, int OMODE>
__global__ void __launch_bounds__(256, 2)
mma_gemm(GemmParams p)
{
    constexpr int A_BYTES = 128 * KPITCH * 2;   // 18432
    constexpr int B_BYTES = NC * KPITCH * 2;
    constexpr int NF = NC / 16;

    extern __shared__ __align__(16) char sm[];
    char* sAhi = sm;
    char* sAlo = sm + A_BYTES;
    char* sBhi = sm + 2 * A_BYTES;
    char* sBlo = sBhi + B_BYTES;
    float* s_stats = (float*)(sBlo + B_BYTES);  // AMODE2: 256 floats

    int tid = threadIdx.x;
    int wid = tid >> 5, lane = tid & 31;

    int z = blockIdx.z;
    int zh = z / p.z_lo, zl = z % p.z_lo;
    const __nv_bfloat16* Bmh = p.Bh + (size_t)zh * p.b_hi + (size_t)zl * p.b_lo;
    const __nv_bfloat16* Bml = p.Bl + (size_t)zh * p.b_hi + (size_t)zl * p.b_lo;

    int m0 = blockIdx.y * 128;
    int n0 = blockIdx.x * NC;

    int warpM = (wid >> 1) * 32;
    int warpN = (wid & 1) * (NC / 2);

    if (AMODE == 2) {
        if (tid < 256)
            s_stats[tid] = p.stats[((size_t)z * L_ + m0) * 2 + tid];
        __syncthreads();
    }

    float acc[2][NF][4];
#pragma unroll
    for (int i = 0; i < 2; i++)
#pragma unroll
        for (int j = 0; j < NF; j++)
#pragma unroll
            for (int r = 0; r < 4; r++) acc[i][j][r] = 0.f;

    for (int ck = 0; ck < p.k_chunks; ck++) {
        int k0 = ck * 64;
        // ---- A tile
        if (AMODE == 0) {
            const float* A = (const float*)p.A + (size_t)zh * p.a_hi + (size_t)zl * p.a_lo;
            for (int g = tid; g < 1024; g += 256) {
                int row = g >> 3, gc = (g & 7) * 8;
                uint4 hi, lo;
                split8(A + (size_t)(m0 + row) * p.lda + k0 + gc, hi, lo);
                int off = row * (KPITCH * 2) + gc * 2;
                *(uint4*)(sAhi + off) = hi;
                *(uint4*)(sAlo + off) = lo;
            }
        } else if (AMODE == 1) {
            const __nv_bfloat16* Ah = (const __nv_bfloat16*)p.A +
                (size_t)zh * p.a_hi + (size_t)zl * p.a_lo;
            const __nv_bfloat16* Al = (const __nv_bfloat16*)p.A2 +
                (size_t)zh * p.a_hi + (size_t)zl * p.a_lo;
            for (int g = tid; g < 1024; g += 256) {
                int row = g >> 3, seg = (g & 7);
                size_t src = (size_t)(m0 + row) * p.lda + k0 + seg * 8;
                int off = row * (KPITCH * 2) + seg * 16;
                *(uint4*)(sAhi + off) = *(const uint4*)(Ah + src);
                *(uint4*)(sAlo + off) = *(const uint4*)(Al + src);
            }
        } else {  // AMODE 2: normalize raw scores, write attn, split
            const float* Asc = (const float*)p.A + (size_t)zh * p.a_hi + (size_t)zl * p.a_lo;
            float* aout = p.attn_out + (size_t)z * L_ * L_;
            for (int g = tid; g < 1024; g += 256) {
                int row = g >> 3, gc = (g & 7) * 8;
                const float* src = Asc + (size_t)(m0 + row) * p.lda + k0 + gc;
                float4 u = *(const float4*)src;
                float4 w = *(const float4*)(src + 4);
                float m = s_stats[row * 2], inv = s_stats[row * 2 + 1];
                float e[8];
                e[0] = __expf(u.x - m) * inv; e[1] = __expf(u.y - m) * inv;
                e[2] = __expf(u.z - m) * inv; e[3] = __expf(u.w - m) * inv;
                e[4] = __expf(w.x - m) * inv; e[5] = __expf(w.y - m) * inv;
                e[6] = __expf(w.z - m) * inv; e[7] = __expf(w.w - m) * inv;
                float* dst = aout + (size_t)(m0 + row) * L_ + k0 + gc;
                *(float4*)dst = make_float4(e[0], e[1], e[2], e[3]);
                *(float4*)(dst + 4) = make_float4(e[4], e[5], e[6], e[7]);
                uint32_t h[4], l[4];
#pragma unroll
                for (int i = 0; i < 4; i++) {
                    uint32_t hp = pack2f(e[2*i], e[2*i+1]);
                    float h0 = __uint_as_float(hp << 16);
                    float h1 = __uint_as_float(hp & 0xFFFF0000u);
                    l[i] = pack2f(e[2*i] - h0, e[2*i+1] - h1);
                    h[i] = hp;
                }
                int off = row * (KPITCH * 2) + gc * 2;
                *(uint4*)(sAhi + off) = make_uint4(h[0], h[1], h[2], h[3]);
                *(uint4*)(sAlo + off) = make_uint4(l[0], l[1], l[2], l[3]);
            }
        }
        // ---- B tile (planes copy)
        for (int g = tid; g < NC * 8; g += 256) {
            int row = g >> 3, seg = (g & 7);
            size_t src = (size_t)(n0 + row) * p.ldb + k0 + seg * 8;
            int off = row * (KPITCH * 2) + seg * 16;
            *(uint4*)(sBhi + off) = *(const uint4*)(Bmh + src);
            *(uint4*)(sBlo + off) = *(const uint4*)(Bml + src);
        }
        __syncthreads();

        int arow = warpM + (lane >> 2);
        int brow = warpN + (lane >> 2);
        int kq   = (lane & 3) * 2;

#pragma unroll
        for (int pass = 0; pass < 3; pass++) {
            const char* Ab = (pass == 2) ? sAlo : sAhi;
            const char* Bb = (pass == 1) ? sBlo : sBhi;
#pragma unroll
            for (int ks = 0; ks < 4; ks++) {
                int kk = ks * 16 + kq;
                uint32_t af[2][4];
#pragma unroll
                for (int mf = 0; mf < 2; mf++) {
                    int r = arow + mf * 16;
                    af[mf][0] = *(const uint32_t*)(Ab + (r     ) * (KPITCH*2) + kk * 2);
                    af[mf][1] = *(const uint32_t*)(Ab + (r + 8 ) * (KPITCH*2) + kk * 2);
                    af[mf][2] = *(const uint32_t*)(Ab + (r     ) * (KPITCH*2) + (kk + 8) * 2);
                    af[mf][3] = *(const uint32_t*)(Ab + (r + 8 ) * (KPITCH*2) + (kk + 8) * 2);
                }
                uint32_t bfr[NF][2];
#pragma unroll
                for (int nf = 0; nf < NF; nf++) {
                    int n = brow + nf * 8;
                    bfr[nf][0] = *(const uint32_t*)(Bb + n * (KPITCH*2) + kk * 2);
                    bfr[nf][1] = *(const uint32_t*)(Bb + n * (KPITCH*2) + (kk + 8) * 2);
                }
#pragma unroll
                for (int mf = 0; mf < 2; mf++)
#pragma unroll
                    for (int nf = 0; nf < NF; nf++)
                        mma16816(acc[mf][nf], af[mf], bfr[nf]);
            }
        }
        __syncthreads();
    }

    // ---- scale accumulators
    if (p.scale != 1.0f) {
#pragma unroll
        for (int i = 0; i < 2; i++)
#pragma unroll
            for (int j = 0; j < NF; j++)
#pragma unroll
                for (int r = 0; r < 4; r++) acc[i][j][r] *= p.scale;
    }

    // ---- store C
#pragma unroll
    for (int nf = 0; nf < NF; nf++) {
        int col = n0 + warpN + nf * 8 + (lane & 3) * 2;
        float b0 = 0.f, b1 = 0.f;
        if (p.bias) {
            float2 bb = *(const float2*)(p.bias + col);
            b0 = bb.x; b1 = bb.y;
        }
#pragma unroll
        for (int mf = 0; mf < 2; mf++) {
            int r = m0 + warpM + mf * 16 + (lane >> 2);
            float v00 = acc[mf][nf][0] + b0;
            float v01 = acc[mf][nf][1] + b1;
            float v10 = acc[mf][nf][2] + b0;
            float v11 = acc[mf][nf][3] + b1;
            if (OMODE == 1) {
                __nv_bfloat16* Ch = (__nv_bfloat16*)p.C + (size_t)zh * p.c_hi + (size_t)zl * p.c_lo;
                __nv_bfloat16* Cl = (__nv_bfloat16*)p.C2 + (size_t)zh * p.c_hi + (size_t)zl * p.c_lo;
                uint32_t hp0 = pack2f(v00, v01);
                uint32_t hp1 = pack2f(v10, v11);
                float a0 = __uint_as_float(hp0 << 16), a1 = __uint_as_float(hp0 & 0xFFFF0000u);
                float a2 = __uint_as_float(hp1 << 16), a3 = __uint_as_float(hp1 & 0xFFFF0000u);
                uint32_t lp0 = pack2f(v00 - a0, v01 - a1);
                uint32_t lp1 = pack2f(v10 - a2, v11 - a3);
                *(uint32_t*)(Ch + (size_t)r * p.ldc + col) = hp0;
                *(uint32_t*)(Ch + (size_t)(r + 8) * p.ldc + col) = hp1;
                *(uint32_t*)(Cl + (size_t)r * p.ldc + col) = lp0;
                *(uint32_t*)(Cl + (size_t)(r + 8) * p.ldc + col) = lp1;
            } else {
                float* C = (float*)p.C + (size_t)zh * p.c_hi + (size_t)zl * p.c_lo;
                *(float2*)(C + (size_t)r * p.ldc + col) = make_float2(v00, v01);
                *(float2*)(C + (size_t)(r + 8) * p.ldc + col) = make_float2(v10, v11);
            }
        }
    }

    // ---- OMODE 2: per-tile row (max, sumexp) partials
    if (OMODE == 2) {
        float* redm = (float*)sm;            // [128][2]
        float* reds = redm + 256;            // [128][2]
        int g = lane >> 2, q = lane & 3;

        float rmax[4];
#pragma unroll
        for (int mf = 0; mf < 2; mf++) {
            float m0v = -1e30f, m1v = -1e30f;
#pragma unroll
            for (int nf = 0; nf < NF; nf++) {
                m0v = fmaxf(m0v, fmaxf(acc[mf][nf][0], acc[mf][nf][1]));
                m1v = fmaxf(m1v, fmaxf(acc[mf][nf][2], acc[mf][nf][3]));
            }
            rmax[mf*2] = m0v; rmax[mf*2+1] = m1v;
        }
#pragma unroll
        for (int i = 0; i < 4; i++) {
            rmax[i] = fmaxf(rmax[i], __shfl_xor_sync(0xFFFFFFFFu, rmax[i], 1));
            rmax[i] = fmaxf(rmax[i], __shfl_xor_sync(0xFFFFFFFFu, rmax[i], 2));
        }
        __syncthreads();
        if (q == 0) {
#pragma unroll
            for (int i = 0; i < 4; i++) {
                int row = warpM + (i >> 1) * 16 + (i & 1) * 8 + g;
                redm[row * 2 + (wid & 1)] = rmax[i];
            }
        }
        __syncthreads();
        float rsum[4];
#pragma unroll
        for (int i = 0; i < 4; i++) {
            int row = warpM + (i >> 1) * 16 + (i & 1) * 8 + g;
            float mm = fmaxf(redm[row * 2], redm[row * 2 + 1]);
            int mf = i >> 1, half = i & 1;
            float s = 0.f;
#pragma unroll
            for (int nf = 0; nf < NF; nf++) {
                s += __expf(acc[mf][nf][half*2]     - mm);
                s += __expf(acc[mf][nf][half*2 + 1] - mm);
            }
            s += __shfl_xor_sync(0xFFFFFFFFu, s, 1);
            s += __shfl_xor_sync(0xFFFFFFFFu, s, 2);
            rsum[i] = s;
        }
        if (q == 0) {
#pragma unroll
            for (int i = 0; i < 4; i++) {
                int row = warpM + (i >> 1) * 16 + (i & 1) * 8 + g;
                reds[row * 2 + (wid & 1)] = rsum[i];
            }
        }
        __syncthreads();
        if (tid < 128) {
            float mm = fmaxf(redm[tid * 2], redm[tid * 2 + 1]);
            float ss = reds[tid * 2] + reds[tid * 2 + 1];
            size_t idx = (size_t)blockIdx.x * NROWS + (size_t)z * L_ + m0 + tid;
            p.pmax[idx] = mm;
            p.psum[idx] = ss;
        }
    }
}

// ===========================================================================
// Weight transpose + split: Wt planes [n][k] from W fp32 [k][n]
// ===========================================================================
__global__ void __launch_bounds__(256)
wsplit_kernel(const float* __restrict__ src,
              __nv_bfloat16* __restrict__ dh, __nv_bfloat16* __restrict__ dl)
{
    __shared__ float t[32][33];
    int c0 = blockIdx.x * 32, r0 = blockIdx.y * 32;
    int tx = threadIdx.x & 31, ty = threadIdx.x >> 5;
#pragma unroll
    for (int i = ty; i < 32; i += 8)
        t[i][tx] = src[(size_t)(r0 + i) * D_ + c0 + tx];
    __syncthreads();
#pragma unroll
    for (int i = ty; i < 32; i += 8) {
        float v = t[tx][i];
        __nv_bfloat16 h = __float2bfloat16(v);
        float lo = v - __bfloat162float(h);
        size_t o = (size_t)(c0 + i) * D_ + r0 + tx;
        dh[o] = h;
        dl[o] = __float2bfloat16(lo);
    }
}

// ===========================================================================
// bf16 plane transpose for V: [B,L,D] -> [B,D,L], z = b*2 + plane
// ===========================================================================
__global__ void __launch_bounds__(256)
vtrans_kernel(const __nv_bfloat16* __restrict__ Vh, const __nv_bfloat16* __restrict__ Vl,
              __nv_bfloat16* __restrict__ Vth, __nv_bfloat16* __restrict__ Vtl)
{
    __shared__ uint16_t t[32][34];
    int z = blockIdx.z;
    int b = z >> 1, plane = z & 1;
    const uint16_t* s = (const uint16_t*)(plane ? Vl : Vh) + (size_t)b * L_ * D_;
    uint16_t* d = (uint16_t*)(plane ? Vtl : Vth) + (size_t)b * D_ * L_;
    int c0 = blockIdx.x * 32, r0 = blockIdx.y * 32;
    int tx = threadIdx.x & 31, ty = threadIdx.x >> 5;
#pragma unroll
    for (int i = ty; i < 32; i += 8)
        t[i][tx] = s[(size_t)(r0 + i) * D_ + c0 + tx];
    __syncthreads();
#pragma unroll
    for (int i = ty; i < 32; i += 8)
        d[(size_t)(c0 + i) * L_ + r0 + tx] = t[tx][i];
}

// ===========================================================================
// Stats reduce: combine 16 per-tile partials -> (max, 1/sum) per row
// ===========================================================================
__global__ void __launch_bounds__(256)
stats_kernel(const float* __restrict__ pmax, const float* __restrict__ psum,
             float* __restrict__ stats)
{
    int r = blockIdx.x * 256 + threadIdx.x;
    if (r >= NROWS) return;
    float m = -1e30f;
#pragma unroll
    for (int t = 0; t < NTILES; t++)
        m = fmaxf(m, pmax[(size_t)t * NROWS + r]);
    float s = 0.f;
#pragma unroll
    for (int t = 0; t < NTILES; t++)
        s += psum[(size_t)t * NROWS + r] * __expf(pmax[(size_t)t * NROWS + r] - m);
    stats[r * 2] = m;
    stats[r * 2 + 1] = 1.0f / s;
}

// ===========================================================================
extern "C" void kernel_launch(void* const* d_in, const int* in_sizes, int n_in,
                              void* d_out, int out_size)
{
    const float* query = (const float*)d_in[0];
    const float* key_  = (const float*)d_in[1];
    const float* value = (const float*)d_in[2];
    const float* Wq    = (const float*)d_in[3];
    const float* bq    = (const float*)d_in[4];
    const float* Wk    = (const float*)d_in[5];
    const float* bk    = (const float*)d_in[6];
    const float* Wv    = (const float*)d_in[7];
    const float* bv    = (const float*)d_in[8];
    const float* Wo    = (const float*)d_in[9];
    const float* bo    = (const float*)d_in[10];

    float* out = (float*)d_out;

    float* scores; cudaGetSymbolAddress((void**)&scores, g_scores);
    float* attn_out;
    if ((long long)out_size >= OUT_ELEMS + ATTN_ELEMS) attn_out = out + OUT_ELEMS;
    else attn_out = scores;   // fallback: normalize in place (same indices, read-before-write)

    __nv_bfloat16 *Qh, *Ql, *Kh, *Kl, *Vh, *Vl, *Vth, *Vtl, *Ch, *Cl, *Wth, *Wtl;
    cudaGetSymbolAddress((void**)&Qh, g_Qh);   cudaGetSymbolAddress((void**)&Ql, g_Ql);
    cudaGetSymbolAddress((void**)&Kh, g_Kh);   cudaGetSymbolAddress((void**)&Kl, g_Kl);
    cudaGetSymbolAddress((void**)&Vh, g_Vh);   cudaGetSymbolAddress((void**)&Vl, g_Vl);
    cudaGetSymbolAddress((void**)&Vth, g_Vth); cudaGetSymbolAddress((void**)&Vtl, g_Vtl);
    cudaGetSymbolAddress((void**)&Ch, g_ctxh); cudaGetSymbolAddress((void**)&Cl, g_ctxl);
    cudaGetSymbolAddress((void**)&Wth, g_Wth); cudaGetSymbolAddress((void**)&Wtl, g_Wtl);
    float *pmax, *psum, *stats;
    cudaGetSymbolAddress((void**)&pmax, g_pmax);
    cudaGetSymbolAddress((void**)&psum, g_psum);
    cudaGetSymbolAddress((void**)&stats, g_stats);

    const int SMEM128 = 4 * (128 * KPITCH * 2);                       // 73728
    const int SMEM_CTX = 2 * (128 * KPITCH * 2) + 2 * (64 * KPITCH * 2) + 1024; // 56320
    cudaFuncSetAttribute(mma_gemm<128,0,1>, cudaFuncAttributeMaxDynamicSharedMemorySize, SMEM128);
    cudaFuncSetAttribute(mma_gemm<128,1,2>, cudaFuncAttributeMaxDynamicSharedMemorySize, SMEM128);
    cudaFuncSetAttribute(mma_gemm<64,2,1>,  cudaFuncAttributeMaxDynamicSharedMemorySize, SMEM_CTX);
    cudaFuncSetAttribute(mma_gemm<128,1,0>, cudaFuncAttributeMaxDynamicSharedMemorySize, SMEM128);

    // 1. Weight transpose + split -> bf16 planes
    wsplit_kernel<<<dim3(32, 32), 256>>>(Wq, Wth + 0*(size_t)D_*D_, Wtl + 0*(size_t)D_*D_);
    wsplit_kernel<<<dim3(32, 32), 256>>>(Wk, Wth + 1*(size_t)D_*D_, Wtl + 1*(size_t)D_*D_);
    wsplit_kernel<<<dim3(32, 32), 256>>>(Wv, Wth + 2*(size_t)D_*D_, Wtl + 2*(size_t)D_*D_);
    wsplit_kernel<<<dim3(32, 32), 256>>>(Wo, Wth + 3*(size_t)D_*D_, Wtl + 3*(size_t)D_*D_);

    // 2. Projections -> bf16 hi/lo planes
    GemmParams pp{};
    pp.lda = D_; pp.ldb = D_; pp.ldc = D_;
    pp.k_chunks = D_ / 64; pp.scale = 1.0f;
    pp.z_lo = 1;
    dim3 pgrid(D_ / 128, M_ / 128, 1);

    GemmParams pq = pp; pq.A = query; pq.Bh = Wth; pq.Bl = Wtl;
    pq.bias = bq; pq.C = Qh; pq.C2 = Ql;
    mma_gemm<128,0,1><<<pgrid, 256, SMEM128>>>(pq);
    GemmParams pk = pp; pk.A = key_; pk.Bh = Wth + 1*(size_t)D_*D_; pk.Bl = Wtl + 1*(size_t)D_*D_;
    pk.bias = bk; pk.C = Kh; pk.C2 = Kl;
    mma_gemm<128,0,1><<<pgrid, 256, SMEM128>>>(pk);
    GemmParams pv = pp; pv.A = value; pv.Bh = Wth + 2*(size_t)D_*D_; pv.Bl = Wtl + 2*(size_t)D_*D_;
    pv.bias = bv; pv.C = Vh; pv.C2 = Vl;
    mma_gemm<128,0,1><<<pgrid, 256, SMEM128>>>(pv);

    // 3. V plane transpose: [B,L,D] -> [B,D,L]
    vtrans_kernel<<<dim3(D_/32, L_/32, B_*2), 256>>>(Vh, Vl, Vth, Vtl);

    // 4. Scores: raw scaled scores + per-tile row partials
    GemmParams ps{};
    ps.A = Qh; ps.A2 = Ql; ps.Bh = Kh; ps.Bl = Kl; ps.bias = nullptr;
    ps.C = scores;
    ps.pmax = pmax; ps.psum = psum;
    ps.lda = D_; ps.ldb = D_; ps.ldc = L_;
    ps.k_chunks = 1; ps.scale = 0.125f;
    ps.z_lo = H_;
    ps.a_hi = (long long)L_ * D_; ps.a_lo = DK_;
    ps.b_hi = (long long)L_ * D_; ps.b_lo = DK_;
    ps.c_hi = (long long)H_ * L_ * L_; ps.c_lo = (long long)L_ * L_;
    mma_gemm<128,1,2><<<dim3(16, 16, B_ * H_), 256, SMEM128>>>(ps);

    // 5. Stats reduce
    stats_kernel<<<NROWS / 256, 256>>>(pmax, psum, stats);

    // 6. ctx: normalize + write attn + ctx = attn @ Vt^T -> bf16 planes
    GemmParams pc{};
    pc.A = scores; pc.Bh = Vth; pc.Bl = Vtl; pc.bias = nullptr;
    pc.C = Ch; pc.C2 = Cl;
    pc.stats = stats; pc.attn_out = attn_out;
    pc.lda = L_; pc.ldb = L_; pc.ldc = D_;
    pc.k_chunks = L_ / 64; pc.scale = 1.0f;
    pc.z_lo = H_;
    pc.a_hi = (long long)H_ * L_ * L_; pc.a_lo = (long long)L_ * L_;
    pc.b_hi = (long long)D_ * L_;      pc.b_lo = (long long)DK_ * L_;
    pc.c_hi = (long long)L_ * D_;      pc.c_lo = DK_;
    mma_gemm<64,2,1><<<dim3(1, 16, B_ * H_), 256, SMEM_CTX>>>(pc);

    // 7. out = ctx @ Wo + bo
    GemmParams po = pp;
    po.A = Ch; po.A2 = Cl;
    po.Bh = Wth + 3*(size_t)D_*D_; po.Bl = Wtl + 3*(size_t)D_*D_;
    po.bias = bo; po.C = out;
    mma_gemm<128,1,0><<<pgrid, 256, SMEM128>>>(po);
}